// round 1
// baseline (speedup 1.0000x reference)
#include <cuda_runtime.h>

// Scratch for per-row means. 256 rows. (No cudaMalloc allowed.)
__device__ float d_row_mean[256];

// Kernel 1: one block per row, compute mean of 50176 floats.
// 50176 = 12544 float4. 512 threads -> 24.5 float4/thread.
__global__ __launch_bounds__(512) void row_mean_kernel(const float* __restrict__ c1, int row_elems) {
    const int row = blockIdx.x;
    const float4* p = reinterpret_cast<const float4*>(c1 + (size_t)row * row_elems);
    const int n4 = row_elems >> 2;  // 12544

    float s = 0.f;
    for (int i = threadIdx.x; i < n4; i += blockDim.x) {
        float4 v = p[i];
        s += (v.x + v.y) + (v.z + v.w);
    }

    // warp reduce
    #pragma unroll
    for (int o = 16; o > 0; o >>= 1)
        s += __shfl_xor_sync(0xffffffffu, s, o);

    __shared__ float warp_sums[16];
    const int lane = threadIdx.x & 31;
    const int wid = threadIdx.x >> 5;
    if (lane == 0) warp_sums[wid] = s;
    __syncthreads();

    if (wid == 0) {
        float t = (lane < (blockDim.x >> 5)) ? warp_sums[lane] : 0.f;
        #pragma unroll
        for (int o = 8; o > 0; o >>= 1)
            t += __shfl_xor_sync(0xffffffffu, t, o);
        if (lane == 0) d_row_mean[row] = t / (float)row_elems;
    }
}

// Kernel 2: out[row, :] = mean[row] * c2[row, :], vectorized float4.
// grid = (row_elems/4/256, 256), block = 256.
__global__ __launch_bounds__(256) void scale_kernel(const float* __restrict__ c2,
                                                    float* __restrict__ out,
                                                    int row_elems) {
    const int row = blockIdx.y;
    const float m = d_row_mean[row];
    const size_t base = (size_t)row * row_elems;
    const float4* src = reinterpret_cast<const float4*>(c2 + base);
    float4* dst = reinterpret_cast<float4*>(out + base);
    const int i = blockIdx.x * blockDim.x + threadIdx.x;
    float4 v = src[i];
    v.x *= m; v.y *= m; v.z *= m; v.w *= m;
    dst[i] = v;
}

extern "C" void kernel_launch(void* const* d_in, const int* in_sizes, int n_in,
                              void* d_out, int out_size) {
    const float* c1 = (const float*)d_in[0];
    const float* c2 = (const float*)d_in[1];
    float* out = (float*)d_out;

    const int B = 256;
    const int row_elems = in_sizes[0] / B;  // 50176

    row_mean_kernel<<<B, 512>>>(c1, row_elems);

    const int n4_per_row = row_elems >> 2;       // 12544
    dim3 grid(n4_per_row / 256, B);              // 49 x 256
    scale_kernel<<<grid, 256>>>(c2, out, row_elems);
}